// round 15
// baseline (speedup 1.0000x reference)
#include <cuda_runtime.h>
#include <cuda_bf16.h>
#include <stdint.h>

// NeuralODE RK4, round 15: gemm1+gemm2 FUSED into one launch per eval with an
// in-kernel producer->consumer dependency. bids 0..255 = gemm1 (m-tile-major:
// bids 16*mt..16*mt+15 finish row-block mt early, bump cnt[mt]); bids 256..383
// = gemm2 (spin on cnt[mt]==16, then R9 64x64 mainloop + RK4 epilogue).
// Deadlock-free: waiters (<=128) < resident slots (296). Graph: 398 nodes.

typedef unsigned int u32;

#define B_DIM 2048
#define F_DIM 256
#define H_DIM 1024
#define BF    (B_DIM * F_DIM)

__device__ __nv_bfloat16 gA0[BF];                // xe hi
__device__ __nv_bfloat16 gA1[BF];                // xe lo
__device__ __nv_bfloat16 gH0[B_DIM * H_DIM];     // h  hi
__device__ __nv_bfloat16 gH1[B_DIM * H_DIM];     // h  lo
__device__ __nv_bfloat16 gW1a[F_DIM * H_DIM];    // W1 body hi [k][n]
__device__ __nv_bfloat16 gW1b[F_DIM * H_DIM];    // W1 body lo
__device__ __nv_bfloat16 gW2a[H_DIM * F_DIM];    // W2 hi      [k][n]
__device__ __nv_bfloat16 gW2b[H_DIM * F_DIM];    // W2 lo
__device__ float g_xc [BF];                      // RK4 base state
__device__ float g_acc[BF];                      // RK4 k-accumulator
__device__ int   g_cnt[16];                      // per-row-block producer counters

__device__ __forceinline__ u32 s2u(const void* p) {
    u32 a;
    asm("{ .reg .u64 t; cvta.to.shared.u64 t, %1; cvt.u32.u64 %0, t; }" : "=r"(a) : "l"(p));
    return a;
}
__device__ __forceinline__ void split2(float v, uint16_t& hi, uint16_t& lo) {
    __nv_bfloat16 b0 = __float2bfloat16_rn(v);
    float r = v - __bfloat162float(b0);
    __nv_bfloat16 b1 = __float2bfloat16_rn(r);
    hi = __nv_bfloat16_raw(b0).x;
    lo = __nv_bfloat16_raw(b1).x;
}
__device__ __forceinline__ void cpa16(u32 dst, const void* src) {
    asm volatile("cp.async.cg.shared.global [%0], [%1], 16;" :: "r"(dst), "l"(src));
}
__device__ __forceinline__ void cpa_commit() { asm volatile("cp.async.commit_group;" ::: "memory"); }
__device__ __forceinline__ void cpwait1() { asm volatile("cp.async.wait_group 1;" ::: "memory"); }
__device__ __forceinline__ void cpwait0() { asm volatile("cp.async.wait_group 0;" ::: "memory"); }

__device__ __forceinline__ void ldsm_a(u32 addr, u32& r0, u32& r1, u32& r2, u32& r3) {
    asm volatile("ldmatrix.sync.aligned.m8n8.x4.shared.b16 {%0,%1,%2,%3}, [%4];"
                 : "=r"(r0), "=r"(r1), "=r"(r2), "=r"(r3) : "r"(addr));
}
__device__ __forceinline__ void ldsm_bt(u32 addr, u32& r0, u32& r1, u32& r2, u32& r3) {
    asm volatile("ldmatrix.sync.aligned.m8n8.x4.trans.shared.b16 {%0,%1,%2,%3}, [%4];"
                 : "=r"(r0), "=r"(r1), "=r"(r2), "=r"(r3) : "r"(addr));
}
__device__ __forceinline__ void mma16816(float* c, const u32* a, u32 b0, u32 b1) {
    asm volatile(
        "mma.sync.aligned.m16n8k16.row.col.f32.bf16.bf16.f32 "
        "{%0,%1,%2,%3}, {%4,%5,%6,%7}, {%8,%9}, {%0,%1,%2,%3};"
        : "+f"(c[0]), "+f"(c[1]), "+f"(c[2]), "+f"(c[3])
        : "r"(a[0]), "r"(a[1]), "r"(a[2]), "r"(a[3]), "r"(b0), "r"(b1));
}

// ---------------- setup ----------------

__global__ void k_conv(const float* __restrict__ W1, const float* __restrict__ W2) {
    int i = blockIdx.x * blockDim.x + threadIdx.x;
    uint16_t a, b;
    if (i < F_DIM * H_DIM) {
        split2(W1[i], a, b);
        ((uint16_t*)gW1a)[i] = a;
        ((uint16_t*)gW1b)[i] = b;
    } else if (i < 2 * F_DIM * H_DIM) {
        int j = i - F_DIM * H_DIM;
        split2(W2[j], a, b);
        ((uint16_t*)gW2a)[j] = a;
        ((uint16_t*)gW2b)[j] = b;
    }
}

__global__ void k_init(const float* __restrict__ x, float* __restrict__ out) {
    int i = blockIdx.x * blockDim.x + threadIdx.x;
    if (i < 16) g_cnt[i] = 0;                 // reset producer counters each replay
    if (i >= BF) return;
    float v = x[i];
    out[i] = v;
    g_xc[i] = v;
    uint16_t a, b; split2(v, a, b);
    ((uint16_t*)gA0)[i] = a;
    ((uint16_t*)gA1)[i] = b;
}

// ---------------- fused eval kernel ----------------
// grid 384, 256 threads, 96KB dyn smem, 2 CTAs/SM.
// bids 0..255:  GEMM1 role, mt = bid>>4, nt = bid&15 (m-tile-major completion)
// bids 256..383: GEMM2+RK4 role, bid2 = bid-256, bx = bid2>>2, by = bid2&3

#define G1_BUF 49152u
#define G2_BUF 32768u

__global__ __launch_bounds__(256, 2) void k_eval(const float* __restrict__ b1,
                                                 const float* __restrict__ wt,
                                                 const float* __restrict__ b2,
                                                 float* __restrict__ out,
                                                 int e, int s, float te, float ae) {
    extern __shared__ __align__(128) unsigned char smem[];
    const u32 sb = s2u(smem);
    const int tid = threadIdx.x, lane = tid & 31, wid = tid >> 5;
    const int wm = wid & 1, wn = wid >> 1;
    const int bid = blockIdx.x;

    const int lr  = (lane & 7) + ((lane >> 3) & 1) * 8;
    const int hk  = lane >> 4;
    const int bsw = lr & 7;
    const int nblk = wn * 2 + hk;

    if (bid < 256) {
        // ================= GEMM1: h = tanh(xe @ W1x + te*wt + b1) =================
        const int mt = bid >> 4, nt = bid & 15;
        const int m0 = mt * 128, n0 = nt * 64;

        float acc[4][2][4];
        #pragma unroll
        for (int i = 0; i < 4; ++i)
            #pragma unroll
            for (int j = 0; j < 2; ++j)
                #pragma unroll
                for (int q = 0; q < 4; ++q) acc[i][j][q] = 0.0f;

        auto issue = [&](int c) {
            int ko = c * 64;
            u32 st = sb + (u32)(c & 1) * G1_BUF;
            #pragma unroll
            for (int t = 0; t < 4; ++t) {           // A planes, 128x64 each
                int cc = tid + t * 256;
                int r = cc >> 3, col = cc & 7;
                u32 off = (u32)r * 128 + (u32)((col ^ (r & 7)) << 4);
                size_t gsrc = (size_t)(m0 + r) * F_DIM + ko + col * 8;
                cpa16(st + off,          gA0 + gsrc);
                cpa16(st + 16384 + off,  gA1 + gsrc);
            }
            #pragma unroll
            for (int t = 0; t < 2; ++t) {           // B planes, 64x64 each
                int cc = tid + t * 256;
                int r = cc >> 3, col = cc & 7;
                u32 off = (u32)r * 128 + (u32)((col ^ (r & 7)) << 4);
                size_t gsrc = (size_t)(ko + r) * H_DIM + n0 + col * 8;
                cpa16(st + 32768 + off,  gW1a + gsrc);
                cpa16(st + 40960 + off,  gW1b + gsrc);
            }
            cpa_commit();
        };

        const int ar0 = wm * 64 + lr;
        const int asw = ar0 & 7;

        issue(0);
        #pragma unroll 1
        for (int c = 0; c < 4; ++c) {
            if (c + 1 < 4) { issue(c + 1); cpwait1(); } else { cpwait0(); }
            __syncthreads();
            u32 st = sb + (u32)(c & 1) * G1_BUF;
            #pragma unroll
            for (int ks = 0; ks < 4; ++ks) {
                u32 acol = (u32)((((ks << 1) + hk) ^ asw) << 4);
                u32 a0[4][4], a1[4][4];
                #pragma unroll
                for (int mi = 0; mi < 4; ++mi) {
                    u32 rowoff = (u32)(ar0 + mi * 16) * 128 + acol;
                    ldsm_a(st + rowoff,         a0[mi][0], a0[mi][1], a0[mi][2], a0[mi][3]);
                    ldsm_a(st + 16384 + rowoff, a1[mi][0], a1[mi][1], a1[mi][2], a1[mi][3]);
                }
                u32 boff = (u32)(ks * 16 + lr) * 128 + (u32)((nblk ^ bsw) << 4);
                u32 b0[2][2], b1v[2][2];
                ldsm_bt(st + 32768 + boff, b0[0][0], b0[0][1], b0[1][0], b0[1][1]);
                ldsm_bt(st + 40960 + boff, b1v[0][0], b1v[0][1], b1v[1][0], b1v[1][1]);
                #pragma unroll
                for (int mi = 0; mi < 4; ++mi)
                    #pragma unroll
                    for (int nb = 0; nb < 2; ++nb)
                        mma16816(acc[mi][nb], a0[mi], b0[nb][0], b0[nb][1]);
                #pragma unroll
                for (int mi = 0; mi < 4; ++mi)
                    #pragma unroll
                    for (int nb = 0; nb < 2; ++nb)
                        mma16816(acc[mi][nb], a1[mi], b0[nb][0], b0[nb][1]);
                #pragma unroll
                for (int mi = 0; mi < 4; ++mi)
                    #pragma unroll
                    for (int nb = 0; nb < 2; ++nb)
                        mma16816(acc[mi][nb], a0[mi], b1v[nb][0], b1v[nb][1]);
            }
            __syncthreads();
        }

        // epilogue: bias + te*wt, tanh, split-2 -> H planes
        const int rbase = m0 + wm * 64 + (lane >> 2);
        const int cbase = n0 + wn * 16 + (lane & 3) * 2;
        #pragma unroll
        for (int nb = 0; nb < 2; ++nb) {
            int j = cbase + nb * 8;
            float2 bb = *(const float2*)(b1 + j);
            float2 ww = *(const float2*)(wt + j);
            float bias0 = bb.x + te * ww.x;
            float bias1 = bb.y + te * ww.y;
            #pragma unroll
            for (int mi = 0; mi < 4; ++mi) {
                #pragma unroll
                for (int h = 0; h < 2; ++h) {
                    int row = rbase + mi * 16 + h * 8;
                    float v0 = tanhf(acc[mi][nb][h * 2]     + bias0);
                    float v1 = tanhf(acc[mi][nb][h * 2 + 1] + bias1);
                    uint16_t h0, l0, h1, l1;
                    split2(v0, h0, l0); split2(v1, h1, l1);
                    size_t o = ((size_t)row * H_DIM + j) >> 1;
                    ((u32*)gH0)[o] = (u32)h0 | ((u32)h1 << 16);
                    ((u32*)gH1)[o] = (u32)l0 | ((u32)l1 << 16);
                }
            }
        }
        // publish: row-block mt has one more finished column tile
        __syncthreads();
        __threadfence();
        if (tid == 0) atomicAdd(&g_cnt[mt], 1);

    } else {
        // ================= GEMM2 + RK4: kvec = h @ W2 + b2 =================
        const int bid2 = bid - 256;
        const int bx = bid2 >> 2, by = bid2 & 3;   // mt-ascending wake order
        const int m0 = bx * 64, n0 = by * 64;
        const int mt = bx >> 1;

        // wait for all 16 producer tiles of this row-block
        if (tid == 0) {
            while (true) {
                int v;
                asm volatile("ld.global.acquire.gpu.b32 %0, [%1];"
                             : "=r"(v) : "l"(&g_cnt[mt]) : "memory");
                if (v >= 16) break;
                __nanosleep(128);
            }
        }
        __syncthreads();
        __threadfence();   // acquire H planes

        float acc[2][2][4];
        #pragma unroll
        for (int i = 0; i < 2; ++i)
            #pragma unroll
            for (int j = 0; j < 2; ++j)
                #pragma unroll
                for (int q = 0; q < 4; ++q) acc[i][j][q] = 0.0f;

        auto issue = [&](int c) {
            int ko = c * 64;
            u32 st = sb + (u32)(c & 1) * G2_BUF;
            #pragma unroll
            for (int t = 0; t < 2; ++t) {           // A planes (H), 64x64 each
                int cc = tid + t * 256;
                int r = cc >> 3, col = cc & 7;
                u32 off = (u32)r * 128 + (u32)((col ^ (r & 7)) << 4);
                size_t gsrc = (size_t)(m0 + r) * H_DIM + ko + col * 8;
                cpa16(st + off,         gH0 + gsrc);
                cpa16(st + 8192 + off,  gH1 + gsrc);
            }
            #pragma unroll
            for (int t = 0; t < 2; ++t) {           // B planes (W2), 64x64 each
                int cc = tid + t * 256;
                int r = cc >> 3, col = cc & 7;
                u32 off = (u32)r * 128 + (u32)((col ^ (r & 7)) << 4);
                size_t gsrc = (size_t)(ko + r) * F_DIM + n0 + col * 8;
                cpa16(st + 16384 + off, gW2a + gsrc);
                cpa16(st + 24576 + off, gW2b + gsrc);
            }
            cpa_commit();
        };

        const int ar0 = wm * 32 + lr;
        const int asw = ar0 & 7;

        issue(0);
        #pragma unroll 1
        for (int c = 0; c < 16; ++c) {
            if (c + 1 < 16) { issue(c + 1); cpwait1(); } else { cpwait0(); }
            __syncthreads();
            u32 st = sb + (u32)(c & 1) * G2_BUF;
            #pragma unroll
            for (int ks = 0; ks < 4; ++ks) {
                u32 acol = (u32)((((ks << 1) + hk) ^ asw) << 4);
                u32 a0[2][4], a1[2][4];
                #pragma unroll
                for (int mi = 0; mi < 2; ++mi) {
                    u32 rowoff = (u32)(ar0 + mi * 16) * 128 + acol;
                    ldsm_a(st + rowoff,        a0[mi][0], a0[mi][1], a0[mi][2], a0[mi][3]);
                    ldsm_a(st + 8192 + rowoff, a1[mi][0], a1[mi][1], a1[mi][2], a1[mi][3]);
                }
                u32 boff = (u32)(ks * 16 + lr) * 128 + (u32)((nblk ^ bsw) << 4);
                u32 b0[2][2], b1v[2][2];
                ldsm_bt(st + 16384 + boff, b0[0][0], b0[0][1], b0[1][0], b0[1][1]);
                ldsm_bt(st + 24576 + boff, b1v[0][0], b1v[0][1], b1v[1][0], b1v[1][1]);
                #pragma unroll
                for (int mi = 0; mi < 2; ++mi)
                    #pragma unroll
                    for (int nb = 0; nb < 2; ++nb)
                        mma16816(acc[mi][nb], a0[mi], b0[nb][0], b0[nb][1]);
                #pragma unroll
                for (int mi = 0; mi < 2; ++mi)
                    #pragma unroll
                    for (int nb = 0; nb < 2; ++nb)
                        mma16816(acc[mi][nb], a1[mi], b0[nb][0], b0[nb][1]);
                #pragma unroll
                for (int mi = 0; mi < 2; ++mi)
                    #pragma unroll
                    for (int nb = 0; nb < 2; ++nb)
                        mma16816(acc[mi][nb], a0[mi], b1v[nb][0], b1v[nb][1]);
            }
            __syncthreads();
        }

        // epilogue: RK4 state machine (CTA uniquely owns its 64x64 tile)
        const float dt6 = (1.0f / 99.0f) / 6.0f;
        const float be = (e == 1 || e == 2) ? 2.0f : 1.0f;
        const int rbase = m0 + wm * 32 + (lane >> 2);
        const int cbase = n0 + wn * 16 + (lane & 3) * 2;
        #pragma unroll
        for (int nb = 0; nb < 2; ++nb) {
            int j = cbase + nb * 8;
            float2 bb = *(const float2*)(b2 + j);
            #pragma unroll
            for (int mi = 0; mi < 2; ++mi) {
                #pragma unroll
                for (int h = 0; h < 2; ++h) {
                    int row = rbase + mi * 16 + h * 8;
                    size_t go = (size_t)row * F_DIM + j;
                    float kv0 = acc[mi][nb][h * 2]     + bb.x;
                    float kv1 = acc[mi][nb][h * 2 + 1] + bb.y;
                    float2 xcv = *(const float2*)&g_xc[go];
                    float a0, a1;
                    if (e == 0) { a0 = kv0; a1 = kv1; }
                    else {
                        float2 av = *(const float2*)&g_acc[go];
                        a0 = av.x + be * kv0; a1 = av.y + be * kv1;
                    }
                    float x0, x1;
                    if (e < 3) {
                        x0 = xcv.x + ae * kv0; x1 = xcv.y + ae * kv1;
                        *(float2*)&g_acc[go] = make_float2(a0, a1);
                    } else {
                        x0 = xcv.x + dt6 * a0; x1 = xcv.y + dt6 * a1;
                        *(float2*)&g_xc[go] = make_float2(x0, x1);
                        *(float2*)&out[(size_t)(s + 1) * BF + go] = make_float2(x0, x1);
                    }
                    uint16_t h0, l0, h1, l1;
                    split2(x0, h0, l0); split2(x1, h1, l1);
                    ((u32*)gA0)[go >> 1] = (u32)h0 | ((u32)h1 << 16);
                    ((u32*)gA1)[go >> 1] = (u32)l0 | ((u32)l1 << 16);
                }
            }
        }
        // reset this row-block's counter for the next eval launch:
        // exactly one consumer CTA per mt does it (bx even, by==0), AFTER its
        // own wait completed; next launch can't observe a stale value because
        // this launch's reset happens-before the kernel boundary.
        if (tid == 0 && by == 0 && (bx & 1) == 0) {
            __threadfence();
            asm volatile("st.global.release.gpu.b32 [%0], %1;"
                         :: "l"(&g_cnt[mt]), "r"(0) : "memory");
        }
    }
}

// ---------------- host ----------------

extern "C" void kernel_launch(void* const* d_in, const int* in_sizes, int n_in,
                              void* d_out, int out_size) {
    (void)in_sizes; (void)n_in; (void)out_size;
    const float* x  = (const float*)d_in[0];
    const float* W1 = (const float*)d_in[1];
    const float* b1 = (const float*)d_in[2];
    const float* W2 = (const float*)d_in[3];
    const float* b2 = (const float*)d_in[4];
    float* out = (float*)d_out;

    cudaFuncSetAttribute(k_eval, cudaFuncAttributeMaxDynamicSharedMemorySize, 2 * G1_BUF);

    k_conv<<<2048, 256>>>(W1, W2);
    k_init<<<2048, 256>>>(x, out);

    const float dt = 1.0f / 99.0f;
    const float* wt = W1 + (size_t)F_DIM * H_DIM;   // time row of W1
    for (int s = 0; s < 99; ++s) {
        float t0 = s * dt;
        const float te_arr[4] = {t0, t0 + 0.5f * dt, t0 + 0.5f * dt, t0 + dt};
        const float ae_arr[4] = {0.5f * dt, 0.5f * dt, dt, 0.0f};
        for (int e = 0; e < 4; ++e) {
            k_eval<<<384, 256, 2 * G1_BUF>>>(b1, wt, b2, out, e, s, te_arr[e], ae_arr[e]);
        }
    }
}

// round 16
// speedup vs baseline: 1.7852x; 1.7852x over previous
#include <cuda_runtime.h>
#include <cuda_fp16.h>
#include <stdint.h>

// NeuralODE RK4, round 16: R12 structure (best known), precision scheme
// switched from bf16/3-pass to FP16/2-pass: activations = single fp16 plane
// (11-bit mantissa), weights = fp16 hi+lo planes (~23-bit). Dropped term is
// x_lo*w ~ 2^-12 relative, incoherent per eval -> predicted final ~6e-5.
// 33% fewer MMAs, 50% less activation traffic. 2 kernels/eval = 794 nodes.

typedef unsigned int u32;

#define B_DIM 2048
#define F_DIM 256
#define H_DIM 1024
#define BF    (B_DIM * F_DIM)

__device__ __half gA  [BF];                    // xe fp16
__device__ __half gH  [B_DIM * H_DIM];         // h  fp16
__device__ __half gW1a[F_DIM * H_DIM];         // W1 body hi [k][n]
__device__ __half gW1b[F_DIM * H_DIM];         // W1 body lo
__device__ __half gW2a[H_DIM * F_DIM];         // W2 hi      [k][n]
__device__ __half gW2b[H_DIM * F_DIM];         // W2 lo
__device__ float g_xc [BF];                    // RK4 base state
__device__ float g_acc[BF];                    // RK4 k-accumulator

__device__ __forceinline__ u32 s2u(const void* p) {
    u32 a;
    asm("{ .reg .u64 t; cvta.to.shared.u64 t, %1; cvt.u32.u64 %0, t; }" : "=r"(a) : "l"(p));
    return a;
}
__device__ __forceinline__ void split2h(float v, uint16_t& hi, uint16_t& lo) {
    __half h0 = __float2half_rn(v);
    float r = v - __half2float(h0);
    __half h1 = __float2half_rn(r);
    hi = __half_raw(h0).x;
    lo = __half_raw(h1).x;
}
__device__ __forceinline__ uint16_t h16(float v) {
    return __half_raw(__float2half_rn(v)).x;
}
__device__ __forceinline__ void cpa16(u32 dst, const void* src) {
    asm volatile("cp.async.cg.shared.global [%0], [%1], 16;" :: "r"(dst), "l"(src));
}
__device__ __forceinline__ void cpa_commit() { asm volatile("cp.async.commit_group;" ::: "memory"); }
__device__ __forceinline__ void cpwait1() { asm volatile("cp.async.wait_group 1;" ::: "memory"); }
__device__ __forceinline__ void cpwait0() { asm volatile("cp.async.wait_group 0;" ::: "memory"); }
__device__ __forceinline__ void bar_wg(int id) {
    asm volatile("bar.sync %0, 256;" :: "r"(id) : "memory");
}

__device__ __forceinline__ void ldsm_a(u32 addr, u32& r0, u32& r1, u32& r2, u32& r3) {
    asm volatile("ldmatrix.sync.aligned.m8n8.x4.shared.b16 {%0,%1,%2,%3}, [%4];"
                 : "=r"(r0), "=r"(r1), "=r"(r2), "=r"(r3) : "r"(addr));
}
__device__ __forceinline__ void ldsm_bt(u32 addr, u32& r0, u32& r1, u32& r2, u32& r3) {
    asm volatile("ldmatrix.sync.aligned.m8n8.x4.trans.shared.b16 {%0,%1,%2,%3}, [%4];"
                 : "=r"(r0), "=r"(r1), "=r"(r2), "=r"(r3) : "r"(addr));
}
__device__ __forceinline__ void mma16816(float* c, const u32* a, u32 b0, u32 b1) {
    asm volatile(
        "mma.sync.aligned.m16n8k16.row.col.f32.f16.f16.f32 "
        "{%0,%1,%2,%3}, {%4,%5,%6,%7}, {%8,%9}, {%0,%1,%2,%3};"
        : "+f"(c[0]), "+f"(c[1]), "+f"(c[2]), "+f"(c[3])
        : "r"(a[0]), "r"(a[1]), "r"(a[2]), "r"(a[3]), "r"(b0), "r"(b1));
}

// ---------------- setup ----------------

__global__ void k_conv(const float* __restrict__ W1, const float* __restrict__ W2) {
    int i = blockIdx.x * blockDim.x + threadIdx.x;
    uint16_t a, b;
    if (i < F_DIM * H_DIM) {
        split2h(W1[i], a, b);
        ((uint16_t*)gW1a)[i] = a;
        ((uint16_t*)gW1b)[i] = b;
    } else if (i < 2 * F_DIM * H_DIM) {
        int j = i - F_DIM * H_DIM;
        split2h(W2[j], a, b);
        ((uint16_t*)gW2a)[j] = a;
        ((uint16_t*)gW2b)[j] = b;
    }
}

__global__ void k_init(const float* __restrict__ x, float* __restrict__ out) {
    int i = blockIdx.x * blockDim.x + threadIdx.x;
    if (i >= BF) return;
    float v = x[i];
    out[i] = v;
    g_xc[i] = v;
    ((uint16_t*)gA)[i] = h16(v);
}

// ---------------- GEMM1: h = tanh(xe @ W1x + te*wt + b1) ----------------
// grid (16,16): CTA 128x64, 4 chunks of k64, 2 stages, 2 CTAs/SM.
// smem per stage: A 16K | B0 8K | B1 8K = 32K; x2 = 64K.

#define G1_BUF 32768u

__global__ __launch_bounds__(256, 2) void k_gemm1(const float* __restrict__ b1,
                                                  const float* __restrict__ wt,
                                                  float te) {
    extern __shared__ __align__(128) unsigned char smem[];
    const u32 sb = s2u(smem);
    const int tid = threadIdx.x, lane = tid & 31, wid = tid >> 5;
    const int wm = wid & 1, wn = wid >> 1;            // 2 x 4 warp grid, tile 64x16
    const int m0 = blockIdx.x * 128, n0 = blockIdx.y * 64;

    float acc[4][2][4];
    #pragma unroll
    for (int i = 0; i < 4; ++i)
        #pragma unroll
        for (int j = 0; j < 2; ++j)
            #pragma unroll
            for (int q = 0; q < 4; ++q) acc[i][j][q] = 0.0f;

    auto issue = [&](int c) {
        int ko = c * 64;
        u32 st = sb + (u32)(c & 1) * G1_BUF;
        #pragma unroll
        for (int t = 0; t < 4; ++t) {           // A plane, 128x64 fp16
            int cc = tid + t * 256;
            int r = cc >> 3, col = cc & 7;
            u32 off = (u32)r * 128 + (u32)((col ^ (r & 7)) << 4);
            cpa16(st + off, gA + (size_t)(m0 + r) * F_DIM + ko + col * 8);
        }
        #pragma unroll
        for (int t = 0; t < 2; ++t) {           // B planes, 64x64 each
            int cc = tid + t * 256;
            int r = cc >> 3, col = cc & 7;
            u32 off = (u32)r * 128 + (u32)((col ^ (r & 7)) << 4);
            size_t gsrc = (size_t)(ko + r) * H_DIM + n0 + col * 8;
            cpa16(st + 16384 + off, gW1a + gsrc);
            cpa16(st + 24576 + off, gW1b + gsrc);
        }
        cpa_commit();
    };

    const int lr  = (lane & 7) + ((lane >> 3) & 1) * 8;
    const int hk  = lane >> 4;
    const int ar0 = wm * 64 + lr;
    const int asw = ar0 & 7;
    const int bsw = lr & 7;
    const int nblk = wn * 2 + hk;

    issue(0);
    #pragma unroll 1
    for (int c = 0; c < 4; ++c) {
        if (c + 1 < 4) { issue(c + 1); cpwait1(); } else { cpwait0(); }
        __syncthreads();
        u32 st = sb + (u32)(c & 1) * G1_BUF;
        #pragma unroll
        for (int ks = 0; ks < 4; ++ks) {
            u32 acol = (u32)((((ks << 1) + hk) ^ asw) << 4);
            u32 a[4][4];
            #pragma unroll
            for (int mi = 0; mi < 4; ++mi) {
                u32 rowoff = (u32)(ar0 + mi * 16) * 128 + acol;
                ldsm_a(st + rowoff, a[mi][0], a[mi][1], a[mi][2], a[mi][3]);
            }
            u32 boff = (u32)(ks * 16 + lr) * 128 + (u32)((nblk ^ bsw) << 4);
            u32 b0[2][2], b1v[2][2];
            ldsm_bt(st + 16384 + boff, b0[0][0], b0[0][1], b0[1][0], b0[1][1]);
            ldsm_bt(st + 24576 + boff, b1v[0][0], b1v[0][1], b1v[1][0], b1v[1][1]);
            #pragma unroll
            for (int mi = 0; mi < 4; ++mi)
                #pragma unroll
                for (int nb = 0; nb < 2; ++nb)
                    mma16816(acc[mi][nb], a[mi], b0[nb][0], b0[nb][1]);
            #pragma unroll
            for (int mi = 0; mi < 4; ++mi)
                #pragma unroll
                for (int nb = 0; nb < 2; ++nb)
                    mma16816(acc[mi][nb], a[mi], b1v[nb][0], b1v[nb][1]);
        }
        __syncthreads();
    }

    // epilogue: bias + te*wt, tanh -> single fp16 H plane
    const int rbase = m0 + wm * 64 + (lane >> 2);
    const int cbase = n0 + wn * 16 + (lane & 3) * 2;
    #pragma unroll
    for (int nb = 0; nb < 2; ++nb) {
        int j = cbase + nb * 8;
        float2 bb = *(const float2*)(b1 + j);
        float2 ww = *(const float2*)(wt + j);
        float bias0 = bb.x + te * ww.x;
        float bias1 = bb.y + te * ww.y;
        #pragma unroll
        for (int mi = 0; mi < 4; ++mi) {
            #pragma unroll
            for (int h = 0; h < 2; ++h) {
                int row = rbase + mi * 16 + h * 8;
                float v0 = tanhf(acc[mi][nb][h * 2]     + bias0);
                float v1 = tanhf(acc[mi][nb][h * 2 + 1] + bias1);
                ((u32*)gH)[((size_t)row * H_DIM + j) >> 1] =
                    (u32)h16(v0) | ((u32)h16(v1) << 16);
            }
        }
    }
}

// ---------------- GEMM2 + RK4: k = h @ W2 + b2 ----------------
// grid (32,4), 512 threads: wg0 does K[0,512), wg1 K[512,1024).
// Each wg: 2-stage pipeline, 8 chunks. smem per stage: A 8K | B0 8K | B1 8K
// = 24K; per wg 48K; total 96K. wg1 spills accs to smem; wg0 reduces + RK4.

#define G2_BUF 24576u

__global__ __launch_bounds__(512, 1) void k_gemm2(const float* __restrict__ b2,
                                                  float* __restrict__ out,
                                                  int e, int s, float ae) {
    extern __shared__ __align__(128) unsigned char smem[];
    const u32 sb = s2u(smem);
    const int tid  = threadIdx.x;
    const int wg   = tid >> 8;                // warpgroup 0/1
    const int ltid = tid & 255;
    const int lane = tid & 31;
    const int lwid = (tid >> 5) & 7;
    const int wm = lwid & 1, wn = lwid >> 1;  // 2 x 4 warp grid, tile 32x16
    const int m0 = blockIdx.x * 64, n0 = blockIdx.y * 64;
    const u32 wbase = sb + (u32)wg * (2 * G2_BUF);
    const int kb = wg * 512;
    const int barid = 1 + wg;

    float acc[2][2][4];
    #pragma unroll
    for (int i = 0; i < 2; ++i)
        #pragma unroll
        for (int j = 0; j < 2; ++j)
            #pragma unroll
            for (int q = 0; q < 4; ++q) acc[i][j][q] = 0.0f;

    auto issue = [&](int c) {
        int ko = kb + c * 64;
        u32 st = wbase + (u32)(c & 1) * G2_BUF;
        #pragma unroll
        for (int t = 0; t < 2; ++t) {           // A plane (H), 64x64 fp16
            int cc = ltid + t * 256;
            int r = cc >> 3, col = cc & 7;
            u32 off = (u32)r * 128 + (u32)((col ^ (r & 7)) << 4);
            cpa16(st + off, gH + (size_t)(m0 + r) * H_DIM + ko + col * 8);
        }
        #pragma unroll
        for (int t = 0; t < 2; ++t) {           // B planes (W2), 64x64 each
            int cc = ltid + t * 256;
            int r = cc >> 3, col = cc & 7;
            u32 off = (u32)r * 128 + (u32)((col ^ (r & 7)) << 4);
            size_t gsrc = (size_t)(ko + r) * F_DIM + n0 + col * 8;
            cpa16(st + 8192 + off,  gW2a + gsrc);
            cpa16(st + 16384 + off, gW2b + gsrc);
        }
        cpa_commit();
    };

    const int lr  = (lane & 7) + ((lane >> 3) & 1) * 8;
    const int hk  = lane >> 4;
    const int ar0 = wm * 32 + lr;
    const int asw = ar0 & 7;
    const int bsw = lr & 7;
    const int nblk = wn * 2 + hk;

    issue(0);
    #pragma unroll 1
    for (int c = 0; c < 8; ++c) {
        if (c + 1 < 8) { issue(c + 1); cpwait1(); } else { cpwait0(); }
        bar_wg(barid);
        u32 st = wbase + (u32)(c & 1) * G2_BUF;
        #pragma unroll
        for (int ks = 0; ks < 4; ++ks) {
            u32 acol = (u32)((((ks << 1) + hk) ^ asw) << 4);
            u32 a[2][4];
            #pragma unroll
            for (int mi = 0; mi < 2; ++mi) {
                u32 rowoff = (u32)(ar0 + mi * 16) * 128 + acol;
                ldsm_a(st + rowoff, a[mi][0], a[mi][1], a[mi][2], a[mi][3]);
            }
            u32 boff = (u32)(ks * 16 + lr) * 128 + (u32)((nblk ^ bsw) << 4);
            u32 b0[2][2], b1v[2][2];
            ldsm_bt(st + 8192 + boff,  b0[0][0], b0[0][1], b0[1][0], b0[1][1]);
            ldsm_bt(st + 16384 + boff, b1v[0][0], b1v[0][1], b1v[1][0], b1v[1][1]);
            #pragma unroll
            for (int mi = 0; mi < 2; ++mi)
                #pragma unroll
                for (int nb = 0; nb < 2; ++nb)
                    mma16816(acc[mi][nb], a[mi], b0[nb][0], b0[nb][1]);
            #pragma unroll
            for (int mi = 0; mi < 2; ++mi)
                #pragma unroll
                for (int nb = 0; nb < 2; ++nb)
                    mma16816(acc[mi][nb], a[mi], b1v[nb][0], b1v[nb][1]);
        }
        bar_wg(barid);
    }

    // ---- intra-CTA split-K reduction ----
    __syncthreads();                 // all mainloop smem reads done -> safe to alias
    float* red = (float*)smem;       // 256 * 17 * 4 = 17408 B, aliases wg0 buffers
    if (wg == 1) {
        int base = ltid * 17;
        #pragma unroll
        for (int mi = 0; mi < 2; ++mi)
            #pragma unroll
            for (int nb = 0; nb < 2; ++nb)
                #pragma unroll
                for (int q = 0; q < 4; ++q)
                    red[base + (mi * 2 + nb) * 4 + q] = acc[mi][nb][q];
    }
    __syncthreads();

    if (wg == 0) {
        int base = ltid * 17;
        #pragma unroll
        for (int mi = 0; mi < 2; ++mi)
            #pragma unroll
            for (int nb = 0; nb < 2; ++nb)
                #pragma unroll
                for (int q = 0; q < 4; ++q)
                    acc[mi][nb][q] += red[base + (mi * 2 + nb) * 4 + q];

        // epilogue: RK4 state machine (CTA uniquely owns its 64x64 tile)
        const float dt6 = (1.0f / 99.0f) / 6.0f;
        const float be = (e == 1 || e == 2) ? 2.0f : 1.0f;
        const int rbase = m0 + wm * 32 + (lane >> 2);
        const int cbase = n0 + wn * 16 + (lane & 3) * 2;
        #pragma unroll
        for (int nb = 0; nb < 2; ++nb) {
            int j = cbase + nb * 8;
            float2 bb = *(const float2*)(b2 + j);
            #pragma unroll
            for (int mi = 0; mi < 2; ++mi) {
                #pragma unroll
                for (int h = 0; h < 2; ++h) {
                    int row = rbase + mi * 16 + h * 8;
                    size_t go = (size_t)row * F_DIM + j;
                    float kv0 = acc[mi][nb][h * 2]     + bb.x;
                    float kv1 = acc[mi][nb][h * 2 + 1] + bb.y;
                    float2 xcv = *(const float2*)&g_xc[go];
                    float a0, a1;
                    if (e == 0) { a0 = kv0; a1 = kv1; }
                    else {
                        float2 av = *(const float2*)&g_acc[go];
                        a0 = av.x + be * kv0; a1 = av.y + be * kv1;
                    }
                    float x0, x1;
                    if (e < 3) {
                        x0 = xcv.x + ae * kv0; x1 = xcv.y + ae * kv1;
                        *(float2*)&g_acc[go] = make_float2(a0, a1);
                    } else {
                        x0 = xcv.x + dt6 * a0; x1 = xcv.y + dt6 * a1;
                        *(float2*)&g_xc[go] = make_float2(x0, x1);
                        *(float2*)&out[(size_t)(s + 1) * BF + go] = make_float2(x0, x1);
                    }
                    ((u32*)gA)[go >> 1] = (u32)h16(x0) | ((u32)h16(x1) << 16);
                }
            }
        }
    }
}

// ---------------- host ----------------

extern "C" void kernel_launch(void* const* d_in, const int* in_sizes, int n_in,
                              void* d_out, int out_size) {
    (void)in_sizes; (void)n_in; (void)out_size;
    const float* x  = (const float*)d_in[0];
    const float* W1 = (const float*)d_in[1];
    const float* b1 = (const float*)d_in[2];
    const float* W2 = (const float*)d_in[3];
    const float* b2 = (const float*)d_in[4];
    float* out = (float*)d_out;

    cudaFuncSetAttribute(k_gemm1, cudaFuncAttributeMaxDynamicSharedMemorySize, 2 * G1_BUF);
    cudaFuncSetAttribute(k_gemm2, cudaFuncAttributeMaxDynamicSharedMemorySize, 4 * G2_BUF);

    k_conv<<<2048, 256>>>(W1, W2);
    k_init<<<2048, 256>>>(x, out);

    const float dt = 1.0f / 99.0f;
    const float* wt = W1 + (size_t)F_DIM * H_DIM;   // time row of W1
    for (int s = 0; s < 99; ++s) {
        float t0 = s * dt;
        const float te_arr[4] = {t0, t0 + 0.5f * dt, t0 + 0.5f * dt, t0 + dt};
        const float ae_arr[4] = {0.5f * dt, 0.5f * dt, dt, 0.0f};
        for (int e = 0; e < 4; ++e) {
            k_gemm1<<<dim3(16, 16), 256, 2 * G1_BUF>>>(b1, wt, te_arr[e]);
            k_gemm2<<<dim3(32, 4), 512, 4 * G2_BUF>>>(b2, out, e, s, ae_arr[e]);
        }
    }
}